// round 13
// baseline (speedup 1.0000x reference)
#include <cuda_runtime.h>
#include <cuda_fp16.h>
#include <math.h>
#include <stdint.h>

#define BATCH  2
#define SEQ    2048
#define DMODEL 2048
#define NH     16
#define NKV    8
#define HD     128
#define KBIG   DMODEL         // 2048: plain fp16 operands (A and W quantized)
#define MROWS  (BATCH * SEQ)  // 4096
#define NQKV   (NH * HD + 2 * NKV * HD)  // 4096 combined QKV columns

// ---------------------------------------------------------------------------
// Scratch (device globals; no allocation allowed)
// ---------------------------------------------------------------------------
__device__ __half g_xh [(size_t)MROWS * DMODEL];      // x quantized to fp16
__device__ __half g_oh [(size_t)MROWS * DMODEL];      // attn out fp16 [m][h*HD+d]
__device__ __half g_wt [(size_t)NQKV * DMODEL];       // [n][k] fp16 (Q|K|V)
__device__ __half g_wot[(size_t)DMODEL * DMODEL];     // [n][k] fp16
__device__ __half g_q[(size_t)BATCH * NH  * SEQ * HD];
__device__ __half g_k[(size_t)BATCH * NKV * SEQ * HD];
__device__ __half g_v[(size_t)BATCH * NKV * SEQ * HD];
__device__ float  g_cos[SEQ * (HD / 2)];
__device__ float  g_sin[SEQ * (HD / 2)];

// ---------------------------------------------------------------------------
// Helpers
// ---------------------------------------------------------------------------
__device__ __forceinline__ uint32_t pack_half2(float a, float b) {
  __half2 h = __floats2half2_rn(a, b);
  return *reinterpret_cast<uint32_t*>(&h);
}

__device__ __forceinline__ float ex2f(float x) {
  float r;
  asm("ex2.approx.f32 %0, %1;" : "=f"(r) : "f"(x));
  return r;
}

#define MMA_16816(C, A, B0, B1)                                              \
  asm volatile(                                                              \
      "mma.sync.aligned.m16n8k16.row.col.f32.f16.f16.f32 "                   \
      "{%0,%1,%2,%3}, {%4,%5,%6,%7}, {%8,%9}, {%0,%1,%2,%3};\n"              \
      : "+f"((C)[0]), "+f"((C)[1]), "+f"((C)[2]), "+f"((C)[3])               \
      : "r"((A)[0]), "r"((A)[1]), "r"((A)[2]), "r"((A)[3]),                  \
        "r"(B0), "r"(B1))

#define LDSM_X4(R0, R1, R2, R3, ADDR)                                        \
  asm volatile(                                                              \
      "ldmatrix.sync.aligned.m8n8.x4.shared.b16 {%0,%1,%2,%3}, [%4];\n"      \
      : "=r"(R0), "=r"(R1), "=r"(R2), "=r"(R3) : "r"(ADDR))

#define LDSM_X4_T(R0, R1, R2, R3, ADDR)                                      \
  asm volatile(                                                              \
      "ldmatrix.sync.aligned.m8n8.x4.trans.shared.b16 {%0,%1,%2,%3}, [%4];\n"\
      : "=r"(R0), "=r"(R1), "=r"(R2), "=r"(R3) : "r"(ADDR))

#define LDSM_X2_T(R0, R1, ADDR)                                              \
  asm volatile(                                                              \
      "ldmatrix.sync.aligned.m8n8.x2.trans.shared.b16 {%0,%1}, [%2];\n"      \
      : "=r"(R0), "=r"(R1) : "r"(ADDR))

#define CP_ASYNC16(DST, SRC)                                                 \
  asm volatile("cp.async.cg.shared.global [%0], [%1], 16;\n" ::              \
                   "r"(DST), "l"(SRC))
#define CP_COMMIT() asm volatile("cp.async.commit_group;\n")
#define CP_WAIT(N)  asm volatile("cp.async.wait_group %0;\n" ::"n"(N))

// ---------------------------------------------------------------------------
// Precompute kernels
// ---------------------------------------------------------------------------
__global__ void rope_init_kernel() {
  int idx = blockIdx.x * blockDim.x + threadIdx.x;
  if (idx < SEQ * (HD / 2)) {
    int s = idx >> 6;
    int i = idx & 63;
    float inv = (float)pow(10000.0, -(double)(2 * i) / (double)HD);
    float a = (float)s * inv;
    g_cos[idx] = cosf(a);
    g_sin[idx] = sinf(a);
  }
}

// x fp32 -> fp16
__global__ void conv_x_kernel(const float* __restrict__ x) {
  int idx = blockIdx.x * blockDim.x + threadIdx.x;
  if (idx < MROWS * DMODEL) {
    float4 v = *(const float4*)(x + (size_t)idx * 4);
    __half2 a = __floats2half2_rn(v.x, v.y);
    __half2 b = __floats2half2_rn(v.z, v.w);
    *(uint2*)(g_xh + (size_t)idx * 4) =
        make_uint2(*(uint32_t*)&a, *(uint32_t*)&b);
  }
}

// W[k][n] fp32 -> Wt[n][k] fp16 (tiled transpose)
__global__ void tw_kernel(const float* __restrict__ W,
                          __half* __restrict__ Wt, int N) {
  __shared__ float tile[32][33];
  const int n0 = blockIdx.x * 32;
  const int k0 = blockIdx.y * 32;
  const int tx = threadIdx.x;
  const int ty = threadIdx.y;
#pragma unroll
  for (int j = 0; j < 32; j += 8)
    tile[ty + j][tx] = W[(size_t)(k0 + ty + j) * N + n0 + tx];
  __syncthreads();
#pragma unroll
  for (int j = 0; j < 32; j += 8) {
    int n = n0 + ty + j;
    int k = k0 + tx;
    Wt[(size_t)n * DMODEL + k] = __float2half_rn(tile[tx][ty + j]);
  }
}

// ---------------------------------------------------------------------------
// Pipelined fp16 GEMM: C[4096, N] = A[4096, 2048] @ Bt[N, 2048]^T
// Block 128x128, BK=64, 3-stage cp.async, 128 threads = 4 warps (2M x 2N),
// warp tile 64x64.
// MODE 0: merged QKV epilogue (rope etc.)   MODE 3: out proj (fp32)
// ---------------------------------------------------------------------------
#define BK      64
#define STRIDE  72
#define STAGE_H (128 * STRIDE)
#define NITERS  (KBIG / BK)   // 32

template <int MODE>
__global__ __launch_bounds__(128) void gemm_f16_kernel(
    const __half* __restrict__ A, const __half* __restrict__ Bt,
    float* __restrict__ out) {
  extern __shared__ __align__(16) __half smem[];
  __half* As = smem;
  __half* Bs = smem + 3 * STAGE_H;

  const int tid  = threadIdx.x;
  const int wid  = tid >> 5;
  const int lane = tid & 31;
  const int wm   = wid >> 1;   // 0..1
  const int wn   = wid & 1;    // 0..1
  const int g    = lane >> 2;
  const int q4   = lane & 3;
  const int m0   = blockIdx.y * 128;
  const int n0   = blockIdx.x * 128;

  const uint32_t as_base = (uint32_t)__cvta_generic_to_shared(As);
  const uint32_t bs_base = (uint32_t)__cvta_generic_to_shared(Bs);

  const int crow = tid >> 3;   // 0..15
  const int cseg = tid & 7;

  const uint32_t a_off =
      (uint32_t)((wm * 64 + (lane & 15)) * STRIDE + (lane >> 4) * 8) * 2;
  const uint32_t b_off =
      (uint32_t)((wn * 64 + (lane & 7) + ((lane & 16) >> 1)) * STRIDE +
                 (lane & 8)) * 2;

  float c[4][8][4];
#pragma unroll
  for (int mt = 0; mt < 4; mt++)
#pragma unroll
    for (int nt = 0; nt < 8; nt++)
#pragma unroll
      for (int j = 0; j < 4; j++) c[mt][nt][j] = 0.f;

  auto load_stage = [&](int stg, int k0) {
    uint32_t abase = as_base + stg * STAGE_H * 2;
    uint32_t bbase = bs_base + stg * STAGE_H * 2;
#pragma unroll
    for (int j = 0; j < 8; j++) {
      int row = j * 16 + crow;
      uint32_t so = (uint32_t)(row * STRIDE + cseg * 8) * 2;
      CP_ASYNC16(abase + so, A + (size_t)(m0 + row) * KBIG + k0 + cseg * 8);
      CP_ASYNC16(bbase + so, Bt + (size_t)(n0 + row) * KBIG + k0 + cseg * 8);
    }
  };

  load_stage(0, 0);
  CP_COMMIT();
  load_stage(1, BK);
  CP_COMMIT();

  for (int it = 0; it < NITERS; it++) {
    CP_WAIT(1);
    __syncthreads();
    if (it + 2 < NITERS) load_stage((it + 2) % 3, (it + 2) * BK);
    CP_COMMIT();

    const int stg = it % 3;
    const uint32_t ab = as_base + stg * STAGE_H * 2 + a_off;
    const uint32_t bb = bs_base + stg * STAGE_H * 2 + b_off;
#pragma unroll
    for (int kt = 0; kt < 4; kt++) {
      const uint32_t ko = kt * 32;
      uint32_t a[4][4];
#pragma unroll
      for (int mt = 0; mt < 4; mt++)
        LDSM_X4(a[mt][0], a[mt][1], a[mt][2], a[mt][3],
                ab + (uint32_t)(mt * 16 * STRIDE * 2) + ko);
#pragma unroll
      for (int p = 0; p < 4; p++) {
        uint32_t b[4];
        LDSM_X4(b[0], b[1], b[2], b[3],
                bb + (uint32_t)(p * 16 * STRIDE * 2) + ko);
#pragma unroll
        for (int mt = 0; mt < 4; mt++) {
          MMA_16816(c[mt][2 * p],     a[mt], b[0], b[1]);
          MMA_16816(c[mt][2 * p + 1], a[mt], b[2], b[3]);
        }
      }
    }
  }

  // Q scale: 1/sqrt(128) * log2(e) — softmax runs in log2 domain (exp2)
  const float qscale = 0.12753102543684988f;
#pragma unroll
  for (int mt = 0; mt < 4; mt++) {
#pragma unroll
    for (int nt = 0; nt < 8; nt++) {
      int col = n0 + wn * 64 + nt * 8 + q4 * 2;
      int row = m0 + wm * 64 + mt * 16 + g;
      if (MODE == 3) {
        *(float2*)&out[(size_t)row * DMODEL + col] =
            make_float2(c[mt][nt][0], c[mt][nt][1]);
        *(float2*)&out[(size_t)(row + 8) * DMODEL + col] =
            make_float2(c[mt][nt][2], c[mt][nt][3]);
      } else {
#pragma unroll
        for (int hh = 0; hh < 2; hh++) {
          int r = row + hh * 8;
          int b = r >> 11;
          int s = r & 2047;
          float v0 = c[mt][nt][hh * 2];
          float v1 = c[mt][nt][hh * 2 + 1];
          __half* dst;
          if (col < NH * HD) {            // Q: rope + scale (incl. log2e)
            int head = col >> 7, d = col & 127;
            int i    = d >> 1;
            float cs = g_cos[s * 64 + i], sn = g_sin[s * 64 + i];
            float r0 = v0 * cs - v1 * sn, r1 = v0 * sn + v1 * cs;
            v0 = r0 * qscale; v1 = r1 * qscale;
            dst = &g_q[(((size_t)(b * NH + head)) * SEQ + s) * HD + d];
          } else if (col < NH * HD + NKV * HD) {  // K: rope
            int kc = col - NH * HD;
            int head = kc >> 7, d = kc & 127;
            int i    = d >> 1;
            float cs = g_cos[s * 64 + i], sn = g_sin[s * 64 + i];
            float r0 = v0 * cs - v1 * sn, r1 = v0 * sn + v1 * cs;
            v0 = r0; v1 = r1;
            dst = &g_k[(((size_t)(b * NKV + head)) * SEQ + s) * HD + d];
          } else {                        // V
            int vc = col - NH * HD - NKV * HD;
            int head = vc >> 7, d = vc & 127;
            dst = &g_v[(((size_t)(b * NKV + head)) * SEQ + s) * HD + d];
          }
          *(__half2*)dst = __floats2half2_rn(v0, v1);
        }
      }
    }
  }
}

// ---------------------------------------------------------------------------
// Flash attention: 1D grid (heavy q-tiles first), 256 threads/block.
// Double-buffered cp.async K/V chunks of 64 rows. log2-domain softmax (exp2);
// row sums computed by tensor core via ones-column in V smem pad (col 128).
// ---------------------------------------------------------------------------
#define AS_ROW 136                 // halves per smem row
#define ABUF_H (128 * AS_ROW)      // halves per buffer (K rows 0-63, V 64-127)

__global__ __launch_bounds__(256) void attn_kernel(const int* __restrict__ causal_flag) {
  extern __shared__ __align__(16) __half S[];  // [2][128][AS_ROW]

  const int tid  = threadIdx.x;
  const int wid  = tid >> 5;
  const int lane = tid & 31;
  const int g    = lane >> 2;
  const int q4   = lane & 3;
  // Heavy-first schedule: qtile decreasing with block id (causal balance)
  const int bid   = blockIdx.x;
  const int qtile = (SEQ / 128) - 1 - (bid >> 5);
  const int hb    = bid & 31;
  const int h     = hb & 15;
  const int b     = hb >> 4;
  const int kv    = h >> 1;
  const int qbase = qtile * 128;
  const int causal = *causal_flag;

  const uint32_t s_base = (uint32_t)__cvta_generic_to_shared(S);
  const uint32_t q_a = s_base +
      (uint32_t)((wid * 16 + (lane & 15)) * AS_ROW + (lane >> 4) * 8) * 2;
  const uint32_t k_b = s_base +
      (uint32_t)(((lane & 7) + ((lane & 16) >> 1)) * AS_ROW + (lane & 8)) * 2;
  const uint32_t v_b = s_base +
      (uint32_t)((64 + (lane & 15)) * AS_ROW + (lane >> 4) * 8) * 2;
  const uint32_t vs_b = s_base +
      (uint32_t)((64 + (lane & 15)) * AS_ROW + 128) * 2;  // ones column

  // Stage Q tile (128 x 128) into buffer 0 and extract A fragments
  const __half* qp = g_q + (((size_t)(b * NH + h)) * SEQ + qbase) * HD;
#pragma unroll
  for (int j = 0; j < 8; j++) {
    int i   = j * 256 + tid;
    int row = i >> 4;
    int seg = i & 15;
    *(uint4*)&S[row * AS_ROW + seg * 8] = *(const uint4*)(qp + row * HD + seg * 8);
  }
  __syncthreads();
  uint32_t qa[8][4];
#pragma unroll
  for (int kt = 0; kt < 8; kt++)
    LDSM_X4(qa[kt][0], qa[kt][1], qa[kt][2], qa[kt][3], q_a + kt * 32);
  // One-time init of V pad cols 128..135 in BOTH buffers: {1, 0, ..., 0}.
  // cp.async chunk loads never touch these bytes, so they persist.
  if (tid < 128) {
    int buf = tid >> 6;
    int row = 64 + (tid & 63);
    *(uint4*)&S[buf * ABUF_H + row * AS_ROW + 128] =
        make_uint4(pack_half2(1.f, 0.f), 0u, 0u, 0u);
  }
  __syncthreads();  // extractions + pad init done before cp.async overwrites

  float o[16][4];
#pragma unroll
  for (int i = 0; i < 16; i++)
#pragma unroll
    for (int j = 0; j < 4; j++) o[i][j] = 0.f;
  float osum[4] = {0.f, 0.f, 0.f, 0.f};   // tensor-core row sums (col 128)
  float m0 = -1e30f, m1 = -1e30f;

  const int jend = causal ? (qbase + 128) : SEQ;
  const int nchunks = jend >> 6;
  const __half* kbp = g_k + ((size_t)(b * NKV + kv)) * SEQ * HD;
  const __half* vbp = g_v + ((size_t)(b * NKV + kv)) * SEQ * HD;
  const int row0 = qbase + wid * 16 + g;
  const int row1 = row0 + 8;

  const int crow = tid >> 4;   // 0..15
  const int cseg = tid & 15;   // 0..15 -> cseg*8 covers all 128 halves

  auto load_chunk = [&](int stg, int j0) {
    uint32_t base = s_base + (uint32_t)stg * ABUF_H * 2;
#pragma unroll
    for (int j = 0; j < 4; j++) {
      int row = j * 16 + crow;   // 0..63
      uint32_t so = (uint32_t)(row * AS_ROW + cseg * 8) * 2;
      CP_ASYNC16(base + so, kbp + (size_t)(j0 + row) * HD + cseg * 8);
      CP_ASYNC16(base + (uint32_t)(64 * AS_ROW * 2) + so,
                 vbp + (size_t)(j0 + row) * HD + cseg * 8);
    }
  };

  load_chunk(0, 0);
  CP_COMMIT();

  for (int ci = 0; ci < nchunks; ci++) {
    const int j0 = ci * 64;
    CP_WAIT(0);
    __syncthreads();
    if (ci + 1 < nchunks) load_chunk((ci + 1) & 1, j0 + 64);
    CP_COMMIT();

    const uint32_t soff = (uint32_t)(ci & 1) * ABUF_H * 2;

    // S = Q @ K^T : per warp 16 x 64 (scores already in log2 domain)
    float sc[8][4];
#pragma unroll
    for (int i = 0; i < 8; i++)
#pragma unroll
      for (int j = 0; j < 4; j++) sc[i][j] = 0.f;
#pragma unroll
    for (int kt = 0; kt < 8; kt++) {
#pragma unroll
      for (int p = 0; p < 4; p++) {
        uint32_t bf[4];
        LDSM_X4(bf[0], bf[1], bf[2], bf[3],
                k_b + soff + (uint32_t)(p * 16 * AS_ROW * 2) + kt * 32);
        MMA_16816(sc[2 * p],     qa[kt], bf[0], bf[1]);
        MMA_16816(sc[2 * p + 1], qa[kt], bf[2], bf[3]);
      }
    }

    if (causal && j0 + 64 > qbase) {
#pragma unroll
      for (int nt = 0; nt < 8; nt++) {
        int col = j0 + nt * 8 + q4 * 2;
        if (col     > row0) sc[nt][0] = -1e30f;
        if (col + 1 > row0) sc[nt][1] = -1e30f;
        if (col     > row1) sc[nt][2] = -1e30f;
        if (col + 1 > row1) sc[nt][3] = -1e30f;
      }
    }

    float r0 = -1e30f, r1 = -1e30f;
#pragma unroll
    for (int nt = 0; nt < 8; nt++) {
      r0 = fmaxf(r0, fmaxf(sc[nt][0], sc[nt][1]));
      r1 = fmaxf(r1, fmaxf(sc[nt][2], sc[nt][3]));
    }
    r0 = fmaxf(r0, __shfl_xor_sync(0xffffffffu, r0, 1));
    r0 = fmaxf(r0, __shfl_xor_sync(0xffffffffu, r0, 2));
    r1 = fmaxf(r1, __shfl_xor_sync(0xffffffffu, r1, 1));
    r1 = fmaxf(r1, __shfl_xor_sync(0xffffffffu, r1, 2));
    float mn0 = fmaxf(m0, r0), mn1 = fmaxf(m1, r1);
    float sf0 = ex2f(m0 - mn0), sf1 = ex2f(m1 - mn1);
    m0 = mn0; m1 = mn1;
#pragma unroll
    for (int nt = 0; nt < 8; nt++) {
      sc[nt][0] = ex2f(sc[nt][0] - mn0);
      sc[nt][1] = ex2f(sc[nt][1] - mn0);
      sc[nt][2] = ex2f(sc[nt][2] - mn1);
      sc[nt][3] = ex2f(sc[nt][3] - mn1);
    }
#pragma unroll
    for (int i = 0; i < 16; i++) {
      o[i][0] *= sf0; o[i][1] *= sf0;
      o[i][2] *= sf1; o[i][3] *= sf1;
    }
    osum[0] *= sf0; osum[1] *= sf0;
    osum[2] *= sf1; osum[3] *= sf1;

    uint32_t pa[4][4];
#pragma unroll
    for (int kt = 0; kt < 4; kt++) {
      pa[kt][0] = pack_half2(sc[2 * kt][0], sc[2 * kt][1]);
      pa[kt][1] = pack_half2(sc[2 * kt][2], sc[2 * kt][3]);
      pa[kt][2] = pack_half2(sc[2 * kt + 1][0], sc[2 * kt + 1][1]);
      pa[kt][3] = pack_half2(sc[2 * kt + 1][2], sc[2 * kt + 1][3]);
    }

    // O += P @ V ; row sums accumulate via ones-column (col 128) mma
#pragma unroll
    for (int kt = 0; kt < 4; kt++) {
#pragma unroll
      for (int pb = 0; pb < 8; pb++) {
        uint32_t bf[4];
        LDSM_X4_T(bf[0], bf[1], bf[2], bf[3],
                  v_b + soff + (uint32_t)(kt * 16 * AS_ROW * 2) + pb * 32);
        MMA_16816(o[2 * pb],     pa[kt], bf[0], bf[1]);
        MMA_16816(o[2 * pb + 1], pa[kt], bf[2], bf[3]);
      }
      uint32_t sb0, sb1;
      LDSM_X2_T(sb0, sb1, vs_b + soff + (uint32_t)(kt * 16 * AS_ROW * 2));
      MMA_16816(osum, pa[kt], sb0, sb1);
    }
  }

  // Row sums live in q4==0 lanes (col 128 of the 8-col tile) — broadcast.
  float l0 = __shfl_sync(0xffffffffu, osum[0], lane & ~3);
  float l1 = __shfl_sync(0xffffffffu, osum[2], lane & ~3);
  float inv0 = 1.f / l0, inv1 = 1.f / l1;
#pragma unroll
  for (int nt = 0; nt < 16; nt++) {
    int d = nt * 8 + q4 * 2;
#pragma unroll
    for (int hh = 0; hh < 2; hh++) {
      int r = (hh == 0) ? row0 : row1;
      float v0 = o[nt][hh * 2]     * (hh == 0 ? inv0 : inv1);
      float v1 = o[nt][hh * 2 + 1] * (hh == 0 ? inv0 : inv1);
      __half* base = g_oh + (size_t)(b * SEQ + r) * DMODEL + h * HD + d;
      *(__half2*)base = __floats2half2_rn(v0, v1);
    }
  }
}

// ---------------------------------------------------------------------------
// Launch
// ---------------------------------------------------------------------------
extern "C" void kernel_launch(void* const* d_in, const int* in_sizes, int n_in,
                              void* d_out, int out_size) {
  const float* x  = (const float*)d_in[0];
  const float* Wq = (const float*)d_in[1];
  const float* Wk = (const float*)d_in[2];
  const float* Wv = (const float*)d_in[3];
  const float* Wo = (const float*)d_in[4];
  const int* is_causal = (const int*)d_in[5];
  float* out = (float*)d_out;

  __half *xh, *oh, *wt, *wot;
  cudaGetSymbolAddress((void**)&xh,  g_xh);
  cudaGetSymbolAddress((void**)&oh,  g_oh);
  cudaGetSymbolAddress((void**)&wt,  g_wt);
  cudaGetSymbolAddress((void**)&wot, g_wot);

  const int gemm_smem = 6 * STAGE_H * 2;   // 110592
  const int attn_smem = 2 * ABUF_H * 2;    // 69632
  cudaFuncSetAttribute(gemm_f16_kernel<0>,
                       cudaFuncAttributeMaxDynamicSharedMemorySize, gemm_smem);
  cudaFuncSetAttribute(gemm_f16_kernel<3>,
                       cudaFuncAttributeMaxDynamicSharedMemorySize, gemm_smem);
  cudaFuncSetAttribute(attn_kernel,
                       cudaFuncAttributeMaxDynamicSharedMemorySize, attn_smem);

  rope_init_kernel<<<(SEQ * 64 + 255) / 256, 256>>>();
  conv_x_kernel<<<(MROWS * DMODEL / 4) / 256, 256>>>(x);
  tw_kernel<<<dim3((NH * HD) / 32, DMODEL / 32), dim3(32, 8)>>>(
      Wq, wt, NH * HD);
  tw_kernel<<<dim3((NKV * HD) / 32, DMODEL / 32), dim3(32, 8)>>>(
      Wk, wt + (size_t)(NH * HD) * DMODEL, NKV * HD);
  tw_kernel<<<dim3((NKV * HD) / 32, DMODEL / 32), dim3(32, 8)>>>(
      Wv, wt + (size_t)(NH * HD + NKV * HD) * DMODEL, NKV * HD);
  tw_kernel<<<dim3(DMODEL / 32, DMODEL / 32), dim3(32, 8)>>>(Wo, wot, DMODEL);

  gemm_f16_kernel<0><<<dim3(NQKV / 128, MROWS / 128), 128, gemm_smem>>>(
      xh, wt, nullptr);

  attn_kernel<<<(SEQ / 128) * NH * BATCH, 256, attn_smem>>>(is_causal);

  gemm_f16_kernel<3><<<dim3(DMODEL / 128, MROWS / 128), 128, gemm_smem>>>(
      oh, wot, out);
}

// round 14
// speedup vs baseline: 1.0648x; 1.0648x over previous
#include <cuda_runtime.h>
#include <cuda_fp16.h>
#include <math.h>
#include <stdint.h>

#define BATCH  2
#define SEQ    2048
#define DMODEL 2048
#define NH     16
#define NKV    8
#define HD     128
#define KBIG   DMODEL         // 2048: plain fp16 operands (A and W quantized)
#define MROWS  (BATCH * SEQ)  // 4096
#define NQKV   (NH * HD + 2 * NKV * HD)  // 4096 combined QKV columns

// ---------------------------------------------------------------------------
// Scratch (device globals; no allocation allowed)
// ---------------------------------------------------------------------------
__device__ __half g_xh [(size_t)MROWS * DMODEL];      // x quantized to fp16
__device__ __half g_oh [(size_t)MROWS * DMODEL];      // attn out fp16 [m][h*HD+d]
__device__ __half g_wt [(size_t)NQKV * DMODEL];       // [n][k] fp16 (Q|K|V)
__device__ __half g_wot[(size_t)DMODEL * DMODEL];     // [n][k] fp16
__device__ __half g_q[(size_t)BATCH * NH  * SEQ * HD];
__device__ __half g_k[(size_t)BATCH * NKV * SEQ * HD];
__device__ __half g_v[(size_t)BATCH * NKV * SEQ * HD];
__device__ float  g_cos[SEQ * (HD / 2)];
__device__ float  g_sin[SEQ * (HD / 2)];

// ---------------------------------------------------------------------------
// Helpers
// ---------------------------------------------------------------------------
__device__ __forceinline__ uint32_t pack_half2(float a, float b) {
  __half2 h = __floats2half2_rn(a, b);
  return *reinterpret_cast<uint32_t*>(&h);
}

__device__ __forceinline__ float ex2f(float x) {
  float r;
  asm("ex2.approx.f32 %0, %1;" : "=f"(r) : "f"(x));
  return r;
}

#define MMA_16816(C, A, B0, B1)                                              \
  asm volatile(                                                              \
      "mma.sync.aligned.m16n8k16.row.col.f32.f16.f16.f32 "                   \
      "{%0,%1,%2,%3}, {%4,%5,%6,%7}, {%8,%9}, {%0,%1,%2,%3};\n"              \
      : "+f"((C)[0]), "+f"((C)[1]), "+f"((C)[2]), "+f"((C)[3])               \
      : "r"((A)[0]), "r"((A)[1]), "r"((A)[2]), "r"((A)[3]),                  \
        "r"(B0), "r"(B1))

#define LDSM_X4(R0, R1, R2, R3, ADDR)                                        \
  asm volatile(                                                              \
      "ldmatrix.sync.aligned.m8n8.x4.shared.b16 {%0,%1,%2,%3}, [%4];\n"      \
      : "=r"(R0), "=r"(R1), "=r"(R2), "=r"(R3) : "r"(ADDR))

#define LDSM_X4_T(R0, R1, R2, R3, ADDR)                                      \
  asm volatile(                                                              \
      "ldmatrix.sync.aligned.m8n8.x4.trans.shared.b16 {%0,%1,%2,%3}, [%4];\n"\
      : "=r"(R0), "=r"(R1), "=r"(R2), "=r"(R3) : "r"(ADDR))

#define LDSM_X2_T(R0, R1, ADDR)                                              \
  asm volatile(                                                              \
      "ldmatrix.sync.aligned.m8n8.x2.trans.shared.b16 {%0,%1}, [%2];\n"      \
      : "=r"(R0), "=r"(R1) : "r"(ADDR))

#define CP_ASYNC16(DST, SRC)                                                 \
  asm volatile("cp.async.cg.shared.global [%0], [%1], 16;\n" ::              \
                   "r"(DST), "l"(SRC))
#define CP_COMMIT() asm volatile("cp.async.commit_group;\n")
#define CP_WAIT(N)  asm volatile("cp.async.wait_group %0;\n" ::"n"(N))

// ---------------------------------------------------------------------------
// Fused precompute: one launch does rope tables, x->fp16, and all 4 weight
// transposes (branch on block-id range; each block takes one uniform path).
//   blocks [0, 512)          : rope tables
//   blocks [512, 8704)       : conv x -> fp16 (4 floats/thread)
//   blocks [8704, 20992)     : 32x32 transpose tiles of Wq|Wk|Wv|Wo
// ---------------------------------------------------------------------------
#define PREP_ROPE_BLKS 512
#define PREP_CONV_BLKS 8192
#define PREP_TW_BLKS   12288
#define PREP_BLKS      (PREP_ROPE_BLKS + PREP_CONV_BLKS + PREP_TW_BLKS)

__global__ __launch_bounds__(256) void prep_kernel(
    const float* __restrict__ x,  const float* __restrict__ Wq,
    const float* __restrict__ Wk, const float* __restrict__ Wv,
    const float* __restrict__ Wo) {
  __shared__ float tile[32][33];
  const int bid = blockIdx.x;
  const int tid = threadIdx.x;

  if (bid < PREP_ROPE_BLKS) {
    int idx = bid * 256 + tid;
    int s = idx >> 6;
    int i = idx & 63;
    float inv = (float)pow(10000.0, -(double)(2 * i) / (double)HD);
    float a = (float)s * inv;
    g_cos[idx] = cosf(a);
    g_sin[idx] = sinf(a);
    return;
  }
  if (bid < PREP_ROPE_BLKS + PREP_CONV_BLKS) {
    int idx = (bid - PREP_ROPE_BLKS) * 256 + tid;
    float4 v = *(const float4*)(x + (size_t)idx * 4);
    __half2 a = __floats2half2_rn(v.x, v.y);
    __half2 b = __floats2half2_rn(v.z, v.w);
    *(uint2*)(g_xh + (size_t)idx * 4) =
        make_uint2(*(uint32_t*)&a, *(uint32_t*)&b);
    return;
  }

  int t = bid - (PREP_ROPE_BLKS + PREP_CONV_BLKS);
  const float* W;
  __half* dst;
  int N;
  if (t < 4096)      { W = Wq; dst = g_wt;                              N = 2048; }
  else if (t < 6144) { t -= 4096; W = Wk; dst = g_wt + (size_t)2048 * DMODEL; N = 1024; }
  else if (t < 8192) { t -= 6144; W = Wv; dst = g_wt + (size_t)3072 * DMODEL; N = 1024; }
  else               { t -= 8192; W = Wo; dst = g_wot;                  N = 2048; }
  const int ntn = N >> 5;
  const int n0 = (t % ntn) * 32;
  const int k0 = (t / ntn) * 32;
  const int tx = tid & 31;
  const int ty = tid >> 5;
#pragma unroll
  for (int j = 0; j < 32; j += 8)
    tile[ty + j][tx] = W[(size_t)(k0 + ty + j) * N + n0 + tx];
  __syncthreads();
#pragma unroll
  for (int j = 0; j < 32; j += 8)
    dst[(size_t)(n0 + ty + j) * DMODEL + k0 + tx] =
        __float2half_rn(tile[tx][ty + j]);
}

// ---------------------------------------------------------------------------
// Pipelined fp16 GEMM: C[4096, N] = A[4096, 2048] @ Bt[N, 2048]^T
// Block 128x128, BK=64, 2-stage cp.async (73.7KB smem -> 3 CTAs/SM),
// 128 threads = 4 warps (2M x 2N), warp tile 64x64.
// MODE 0: merged QKV epilogue (rope etc.)   MODE 3: out proj (fp32)
// ---------------------------------------------------------------------------
#define BK      64
#define STRIDE  72
#define STAGE_H (128 * STRIDE)
#define NSTAGE  2
#define NITERS  (KBIG / BK)   // 32

template <int MODE>
__global__ __launch_bounds__(128, 3) void gemm_f16_kernel(
    const __half* __restrict__ A, const __half* __restrict__ Bt,
    float* __restrict__ out) {
  extern __shared__ __align__(16) __half smem[];
  __half* As = smem;
  __half* Bs = smem + NSTAGE * STAGE_H;

  const int tid  = threadIdx.x;
  const int wid  = tid >> 5;
  const int lane = tid & 31;
  const int wm   = wid >> 1;   // 0..1
  const int wn   = wid & 1;    // 0..1
  const int g    = lane >> 2;
  const int q4   = lane & 3;
  const int m0   = blockIdx.y * 128;
  const int n0   = blockIdx.x * 128;

  const uint32_t as_base = (uint32_t)__cvta_generic_to_shared(As);
  const uint32_t bs_base = (uint32_t)__cvta_generic_to_shared(Bs);

  const int crow = tid >> 3;   // 0..15
  const int cseg = tid & 7;

  const uint32_t a_off =
      (uint32_t)((wm * 64 + (lane & 15)) * STRIDE + (lane >> 4) * 8) * 2;
  const uint32_t b_off =
      (uint32_t)((wn * 64 + (lane & 7) + ((lane & 16) >> 1)) * STRIDE +
                 (lane & 8)) * 2;

  float c[4][8][4];
#pragma unroll
  for (int mt = 0; mt < 4; mt++)
#pragma unroll
    for (int nt = 0; nt < 8; nt++)
#pragma unroll
      for (int j = 0; j < 4; j++) c[mt][nt][j] = 0.f;

  auto load_stage = [&](int stg, int k0) {
    uint32_t abase = as_base + stg * STAGE_H * 2;
    uint32_t bbase = bs_base + stg * STAGE_H * 2;
#pragma unroll
    for (int j = 0; j < 8; j++) {
      int row = j * 16 + crow;
      uint32_t so = (uint32_t)(row * STRIDE + cseg * 8) * 2;
      CP_ASYNC16(abase + so, A + (size_t)(m0 + row) * KBIG + k0 + cseg * 8);
      CP_ASYNC16(bbase + so, Bt + (size_t)(n0 + row) * KBIG + k0 + cseg * 8);
    }
  };

  load_stage(0, 0);
  CP_COMMIT();
  load_stage(1, BK);
  CP_COMMIT();

  for (int it = 0; it < NITERS; it++) {
    CP_WAIT(1);
    __syncthreads();

    const int stg = it & 1;
    const uint32_t ab = as_base + stg * STAGE_H * 2 + a_off;
    const uint32_t bb = bs_base + stg * STAGE_H * 2 + b_off;
#pragma unroll
    for (int kt = 0; kt < 4; kt++) {
      const uint32_t ko = kt * 32;
      uint32_t a[4][4];
#pragma unroll
      for (int mt = 0; mt < 4; mt++)
        LDSM_X4(a[mt][0], a[mt][1], a[mt][2], a[mt][3],
                ab + (uint32_t)(mt * 16 * STRIDE * 2) + ko);
#pragma unroll
      for (int p = 0; p < 4; p++) {
        uint32_t b[4];
        LDSM_X4(b[0], b[1], b[2], b[3],
                bb + (uint32_t)(p * 16 * STRIDE * 2) + ko);
#pragma unroll
        for (int mt = 0; mt < 4; mt++) {
          MMA_16816(c[mt][2 * p],     a[mt], b[0], b[1]);
          MMA_16816(c[mt][2 * p + 1], a[mt], b[2], b[3]);
        }
      }
    }

    __syncthreads();   // all reads of stage it done before its overwrite
    if (it + 2 < NITERS) load_stage(stg, (it + 2) * BK);
    CP_COMMIT();       // always commit: keeps WAIT(1) group accounting exact
  }

  // Q scale: 1/sqrt(128) * log2(e) — softmax runs in log2 domain (exp2)
  const float qscale = 0.12753102543684988f;
#pragma unroll
  for (int mt = 0; mt < 4; mt++) {
#pragma unroll
    for (int nt = 0; nt < 8; nt++) {
      int col = n0 + wn * 64 + nt * 8 + q4 * 2;
      int row = m0 + wm * 64 + mt * 16 + g;
      if (MODE == 3) {
        *(float2*)&out[(size_t)row * DMODEL + col] =
            make_float2(c[mt][nt][0], c[mt][nt][1]);
        *(float2*)&out[(size_t)(row + 8) * DMODEL + col] =
            make_float2(c[mt][nt][2], c[mt][nt][3]);
      } else {
#pragma unroll
        for (int hh = 0; hh < 2; hh++) {
          int r = row + hh * 8;
          int b = r >> 11;
          int s = r & 2047;
          float v0 = c[mt][nt][hh * 2];
          float v1 = c[mt][nt][hh * 2 + 1];
          __half* dst;
          if (col < NH * HD) {            // Q: rope + scale (incl. log2e)
            int head = col >> 7, d = col & 127;
            int i    = d >> 1;
            float cs = g_cos[s * 64 + i], sn = g_sin[s * 64 + i];
            float r0 = v0 * cs - v1 * sn, r1 = v0 * sn + v1 * cs;
            v0 = r0 * qscale; v1 = r1 * qscale;
            dst = &g_q[(((size_t)(b * NH + head)) * SEQ + s) * HD + d];
          } else if (col < NH * HD + NKV * HD) {  // K: rope
            int kc = col - NH * HD;
            int head = kc >> 7, d = kc & 127;
            int i    = d >> 1;
            float cs = g_cos[s * 64 + i], sn = g_sin[s * 64 + i];
            float r0 = v0 * cs - v1 * sn, r1 = v0 * sn + v1 * cs;
            v0 = r0; v1 = r1;
            dst = &g_k[(((size_t)(b * NKV + head)) * SEQ + s) * HD + d];
          } else {                        // V
            int vc = col - NH * HD - NKV * HD;
            int head = vc >> 7, d = vc & 127;
            dst = &g_v[(((size_t)(b * NKV + head)) * SEQ + s) * HD + d];
          }
          *(__half2*)dst = __floats2half2_rn(v0, v1);
        }
      }
    }
  }
}

// ---------------------------------------------------------------------------
// Flash attention: 1D grid (heavy q-tiles first), 256 threads/block.
// Double-buffered cp.async K/V chunks of 64 rows. log2-domain softmax (exp2);
// row sums computed by tensor core via ones-column in V smem pad (col 128).
// ---------------------------------------------------------------------------
#define AS_ROW 136                 // halves per smem row
#define ABUF_H (128 * AS_ROW)      // halves per buffer (K rows 0-63, V 64-127)

__global__ __launch_bounds__(256) void attn_kernel(const int* __restrict__ causal_flag) {
  extern __shared__ __align__(16) __half S[];  // [2][128][AS_ROW]

  const int tid  = threadIdx.x;
  const int wid  = tid >> 5;
  const int lane = tid & 31;
  const int g    = lane >> 2;
  const int q4   = lane & 3;
  // Heavy-first schedule: qtile decreasing with block id (causal balance)
  const int bid   = blockIdx.x;
  const int qtile = (SEQ / 128) - 1 - (bid >> 5);
  const int hb    = bid & 31;
  const int h     = hb & 15;
  const int b     = hb >> 4;
  const int kv    = h >> 1;
  const int qbase = qtile * 128;
  const int causal = *causal_flag;

  const uint32_t s_base = (uint32_t)__cvta_generic_to_shared(S);
  const uint32_t q_a = s_base +
      (uint32_t)((wid * 16 + (lane & 15)) * AS_ROW + (lane >> 4) * 8) * 2;
  const uint32_t k_b = s_base +
      (uint32_t)(((lane & 7) + ((lane & 16) >> 1)) * AS_ROW + (lane & 8)) * 2;
  const uint32_t v_b = s_base +
      (uint32_t)((64 + (lane & 15)) * AS_ROW + (lane >> 4) * 8) * 2;
  const uint32_t vs_b = s_base +
      (uint32_t)((64 + (lane & 15)) * AS_ROW + 128) * 2;  // ones column

  // Stage Q tile (128 x 128) into buffer 0 and extract A fragments
  const __half* qp = g_q + (((size_t)(b * NH + h)) * SEQ + qbase) * HD;
#pragma unroll
  for (int j = 0; j < 8; j++) {
    int i   = j * 256 + tid;
    int row = i >> 4;
    int seg = i & 15;
    *(uint4*)&S[row * AS_ROW + seg * 8] = *(const uint4*)(qp + row * HD + seg * 8);
  }
  __syncthreads();
  uint32_t qa[8][4];
#pragma unroll
  for (int kt = 0; kt < 8; kt++)
    LDSM_X4(qa[kt][0], qa[kt][1], qa[kt][2], qa[kt][3], q_a + kt * 32);
  // One-time init of V pad cols 128..135 in BOTH buffers: {1, 0, ..., 0}.
  // cp.async chunk loads never touch these bytes, so they persist.
  if (tid < 128) {
    int buf = tid >> 6;
    int row = 64 + (tid & 63);
    *(uint4*)&S[buf * ABUF_H + row * AS_ROW + 128] =
        make_uint4(pack_half2(1.f, 0.f), 0u, 0u, 0u);
  }
  __syncthreads();  // extractions + pad init done before cp.async overwrites

  float o[16][4];
#pragma unroll
  for (int i = 0; i < 16; i++)
#pragma unroll
    for (int j = 0; j < 4; j++) o[i][j] = 0.f;
  float osum[4] = {0.f, 0.f, 0.f, 0.f};   // tensor-core row sums (col 128)
  float m0 = -1e30f, m1 = -1e30f;

  const int jend = causal ? (qbase + 128) : SEQ;
  const int nchunks = jend >> 6;
  const __half* kbp = g_k + ((size_t)(b * NKV + kv)) * SEQ * HD;
  const __half* vbp = g_v + ((size_t)(b * NKV + kv)) * SEQ * HD;
  const int row0 = qbase + wid * 16 + g;
  const int row1 = row0 + 8;

  const int crow = tid >> 4;   // 0..15
  const int cseg = tid & 15;   // 0..15 -> cseg*8 covers all 128 halves

  auto load_chunk = [&](int stg, int j0) {
    uint32_t base = s_base + (uint32_t)stg * ABUF_H * 2;
#pragma unroll
    for (int j = 0; j < 4; j++) {
      int row = j * 16 + crow;   // 0..63
      uint32_t so = (uint32_t)(row * AS_ROW + cseg * 8) * 2;
      CP_ASYNC16(base + so, kbp + (size_t)(j0 + row) * HD + cseg * 8);
      CP_ASYNC16(base + (uint32_t)(64 * AS_ROW * 2) + so,
                 vbp + (size_t)(j0 + row) * HD + cseg * 8);
    }
  };

  load_chunk(0, 0);
  CP_COMMIT();

  for (int ci = 0; ci < nchunks; ci++) {
    const int j0 = ci * 64;
    CP_WAIT(0);
    __syncthreads();
    if (ci + 1 < nchunks) load_chunk((ci + 1) & 1, j0 + 64);
    CP_COMMIT();

    const uint32_t soff = (uint32_t)(ci & 1) * ABUF_H * 2;

    // S = Q @ K^T : per warp 16 x 64 (scores already in log2 domain)
    float sc[8][4];
#pragma unroll
    for (int i = 0; i < 8; i++)
#pragma unroll
      for (int j = 0; j < 4; j++) sc[i][j] = 0.f;
#pragma unroll
    for (int kt = 0; kt < 8; kt++) {
#pragma unroll
      for (int p = 0; p < 4; p++) {
        uint32_t bf[4];
        LDSM_X4(bf[0], bf[1], bf[2], bf[3],
                k_b + soff + (uint32_t)(p * 16 * AS_ROW * 2) + kt * 32);
        MMA_16816(sc[2 * p],     qa[kt], bf[0], bf[1]);
        MMA_16816(sc[2 * p + 1], qa[kt], bf[2], bf[3]);
      }
    }

    if (causal && j0 + 64 > qbase) {
#pragma unroll
      for (int nt = 0; nt < 8; nt++) {
        int col = j0 + nt * 8 + q4 * 2;
        if (col     > row0) sc[nt][0] = -1e30f;
        if (col + 1 > row0) sc[nt][1] = -1e30f;
        if (col     > row1) sc[nt][2] = -1e30f;
        if (col + 1 > row1) sc[nt][3] = -1e30f;
      }
    }

    float r0 = -1e30f, r1 = -1e30f;
#pragma unroll
    for (int nt = 0; nt < 8; nt++) {
      r0 = fmaxf(r0, fmaxf(sc[nt][0], sc[nt][1]));
      r1 = fmaxf(r1, fmaxf(sc[nt][2], sc[nt][3]));
    }
    r0 = fmaxf(r0, __shfl_xor_sync(0xffffffffu, r0, 1));
    r0 = fmaxf(r0, __shfl_xor_sync(0xffffffffu, r0, 2));
    r1 = fmaxf(r1, __shfl_xor_sync(0xffffffffu, r1, 1));
    r1 = fmaxf(r1, __shfl_xor_sync(0xffffffffu, r1, 2));
    float mn0 = fmaxf(m0, r0), mn1 = fmaxf(m1, r1);
    float sf0 = ex2f(m0 - mn0), sf1 = ex2f(m1 - mn1);
    m0 = mn0; m1 = mn1;
#pragma unroll
    for (int nt = 0; nt < 8; nt++) {
      sc[nt][0] = ex2f(sc[nt][0] - mn0);
      sc[nt][1] = ex2f(sc[nt][1] - mn0);
      sc[nt][2] = ex2f(sc[nt][2] - mn1);
      sc[nt][3] = ex2f(sc[nt][3] - mn1);
    }
#pragma unroll
    for (int i = 0; i < 16; i++) {
      o[i][0] *= sf0; o[i][1] *= sf0;
      o[i][2] *= sf1; o[i][3] *= sf1;
    }
    osum[0] *= sf0; osum[1] *= sf0;
    osum[2] *= sf1; osum[3] *= sf1;

    uint32_t pa[4][4];
#pragma unroll
    for (int kt = 0; kt < 4; kt++) {
      pa[kt][0] = pack_half2(sc[2 * kt][0], sc[2 * kt][1]);
      pa[kt][1] = pack_half2(sc[2 * kt][2], sc[2 * kt][3]);
      pa[kt][2] = pack_half2(sc[2 * kt + 1][0], sc[2 * kt + 1][1]);
      pa[kt][3] = pack_half2(sc[2 * kt + 1][2], sc[2 * kt + 1][3]);
    }

    // O += P @ V ; row sums accumulate via ones-column (col 128) mma
#pragma unroll
    for (int kt = 0; kt < 4; kt++) {
#pragma unroll
      for (int pb = 0; pb < 8; pb++) {
        uint32_t bf[4];
        LDSM_X4_T(bf[0], bf[1], bf[2], bf[3],
                  v_b + soff + (uint32_t)(kt * 16 * AS_ROW * 2) + pb * 32);
        MMA_16816(o[2 * pb],     pa[kt], bf[0], bf[1]);
        MMA_16816(o[2 * pb + 1], pa[kt], bf[2], bf[3]);
      }
      uint32_t sb0, sb1;
      LDSM_X2_T(sb0, sb1, vs_b + soff + (uint32_t)(kt * 16 * AS_ROW * 2));
      MMA_16816(osum, pa[kt], sb0, sb1);
    }
  }

  // Row sums live in q4==0 lanes (col 128 of the 8-col tile) — broadcast.
  float l0 = __shfl_sync(0xffffffffu, osum[0], lane & ~3);
  float l1 = __shfl_sync(0xffffffffu, osum[2], lane & ~3);
  float inv0 = 1.f / l0, inv1 = 1.f / l1;
#pragma unroll
  for (int nt = 0; nt < 16; nt++) {
    int d = nt * 8 + q4 * 2;
#pragma unroll
    for (int hh = 0; hh < 2; hh++) {
      int r = (hh == 0) ? row0 : row1;
      float v0 = o[nt][hh * 2]     * (hh == 0 ? inv0 : inv1);
      float v1 = o[nt][hh * 2 + 1] * (hh == 0 ? inv0 : inv1);
      __half* base = g_oh + (size_t)(b * SEQ + r) * DMODEL + h * HD + d;
      *(__half2*)base = __floats2half2_rn(v0, v1);
    }
  }
}

// ---------------------------------------------------------------------------
// Launch
// ---------------------------------------------------------------------------
extern "C" void kernel_launch(void* const* d_in, const int* in_sizes, int n_in,
                              void* d_out, int out_size) {
  const float* x  = (const float*)d_in[0];
  const float* Wq = (const float*)d_in[1];
  const float* Wk = (const float*)d_in[2];
  const float* Wv = (const float*)d_in[3];
  const float* Wo = (const float*)d_in[4];
  const int* is_causal = (const int*)d_in[5];
  float* out = (float*)d_out;

  __half *xh, *oh, *wt, *wot;
  cudaGetSymbolAddress((void**)&xh,  g_xh);
  cudaGetSymbolAddress((void**)&oh,  g_oh);
  cudaGetSymbolAddress((void**)&wt,  g_wt);
  cudaGetSymbolAddress((void**)&wot, g_wot);

  const int gemm_smem = 2 * NSTAGE * STAGE_H * 2;   // 73728 -> 3 CTAs/SM
  const int attn_smem = 2 * ABUF_H * 2;             // 69632
  cudaFuncSetAttribute(gemm_f16_kernel<0>,
                       cudaFuncAttributeMaxDynamicSharedMemorySize, gemm_smem);
  cudaFuncSetAttribute(gemm_f16_kernel<3>,
                       cudaFuncAttributeMaxDynamicSharedMemorySize, gemm_smem);
  cudaFuncSetAttribute(attn_kernel,
                       cudaFuncAttributeMaxDynamicSharedMemorySize, attn_smem);

  prep_kernel<<<PREP_BLKS, 256>>>(x, Wq, Wk, Wv, Wo);

  gemm_f16_kernel<0><<<dim3(NQKV / 128, MROWS / 128), 128, gemm_smem>>>(
      xh, wt, nullptr);

  attn_kernel<<<(SEQ / 128) * NH * BATCH, 256, attn_smem>>>(is_causal);

  gemm_f16_kernel<3><<<dim3(DMODEL / 128, MROWS / 128), 128, gemm_smem>>>(
      oh, wot, out);
}